// round 7
// baseline (speedup 1.0000x reference)
#include <cuda_runtime.h>

#define IN_DIM    20
#define HID       6
#define OUT_DIM   6
#define THREADS   128
#define NWARPS    (THREADS / 32)
#define WT_ROWS   64                         // rows per warp-tile (2 per lane)
#define WT_F4     (WT_ROWS * IN_DIM / 4)     // 320 float4 per warp-tile
#define F4_PL     (WT_F4 / 32)               // 10 float4 per lane
#define WT_FLOATS (WT_ROWS * IN_DIM)         // 1280 floats = 5120 B

typedef unsigned long long u64;

__device__ __forceinline__ unsigned smem_u32(const void* p) {
    return (unsigned)__cvta_generic_to_shared(p);
}
__device__ __forceinline__ void cp16(unsigned dst, const void* src) {
    asm volatile("cp.async.cg.shared.global [%0], [%1], 16;\n" :: "r"(dst), "l"(src));
}
__device__ __forceinline__ void cp_commit() {
    asm volatile("cp.async.commit_group;\n" ::: "memory");
}
template <int N>
__device__ __forceinline__ void cp_wait() {
    asm volatile("cp.async.wait_group %0;\n" :: "n"(N) : "memory");
}
__device__ __forceinline__ void stg_cs_v2(float2* p, float2 v) {
    asm volatile("st.global.cs.v2.f32 [%0], {%1, %2};\n" :: "l"(p), "f"(v.x), "f"(v.y));
}

// ---- packed f32x2 helpers (ptxas never emits FFMA2 from C++) ----
__device__ __forceinline__ u64 pack2(float lo, float hi) {
    u64 r; asm("mov.b64 %0, {%1, %2};" : "=l"(r) : "f"(lo), "f"(hi)); return r;
}
__device__ __forceinline__ float hadd2(u64 v) {
    float lo, hi; asm("mov.b64 {%0, %1}, %2;" : "=f"(lo), "=f"(hi) : "l"(v));
    return lo + hi;
}
__device__ __forceinline__ void ffma2(u64& acc, u64 a, u64 b) {
    asm("fma.rn.f32x2 %0, %1, %2, %0;" : "+l"(acc) : "l"(a), "l"(b));
}

// sigmoid(z) = 0.5 * tanh(0.5 z) + 0.5   -> 1 MUFU.TANH + FMUL + FFMA
__device__ __forceinline__ float sigmoid_t(float z) {
    float th;
    asm("tanh.approx.f32 %0, %1;" : "=f"(th) : "f"(z * 0.5f));
    return fmaf(th, 0.5f, 0.5f);
}

__global__ __launch_bounds__(THREADS, 5)
void mlp3_kernel(const float* __restrict__ x,
                 const float* __restrict__ W1,   // [HID, IN]
                 const float* __restrict__ W2,   // [HID, HID]
                 const float* __restrict__ W5,   // [OUT, HID]
                 float* __restrict__ out,        // [B, OUT]
                 int B, int nwt)
{
    __shared__ __align__(16) float sW1[HID * IN_DIM];   // [6][20] rows 80B
    __shared__ __align__(16) float sW2[HID * 8];        // [6][8] zero-padded
    __shared__ __align__(16) float sW5[OUT_DIM * 8];    // [6][8] zero-padded
    extern __shared__ __align__(16) float sX[];         // [NWARPS][2][WT_FLOATS]

    const int t = threadIdx.x;
    const int w = t >> 5;
    const int l = t & 31;

    if (t < HID * IN_DIM) sW1[t] = W1[t];
    if (t < HID * 8)      sW2[t] = ((t & 7) < HID) ? W2[(t >> 3) * HID + (t & 7)] : 0.0f;
    if (t < OUT_DIM * 8)  sW5[t] = ((t & 7) < HID) ? W5[(t >> 3) * HID + (t & 7)] : 0.0f;

    const size_t total_f4 = ((size_t)B * IN_DIM) >> 2;
    float* mybuf0 = &sX[(size_t)(w * 2) * WT_FLOATS];

    auto stage = [&](int wt, int buf) {
        size_t base_f4 = (size_t)wt * WT_F4;
        const float4* src = reinterpret_cast<const float4*>(x) + base_f4;
        unsigned dst = smem_u32(mybuf0 + (size_t)buf * WT_FLOATS);
#pragma unroll
        for (int q = 0; q < F4_PL; ++q) {
            int idx = l + q * 32;
            if (base_f4 + (size_t)idx < total_f4)
                cp16(dst + (unsigned)idx * 16, src + idx);
        }
    };

    const int wstride = gridDim.x * NWARPS;
    int wt = blockIdx.x * NWARPS + w;

    if (wt < nwt) stage(wt, 0);
    cp_commit();

    __syncthreads();   // weights visible before first compute

    int buf = 0;
    for (; wt < nwt; wt += wstride, buf ^= 1) {
        int nxt = wt + wstride;
        if (nxt < nwt) stage(nxt, buf ^ 1);
        cp_commit();
        cp_wait<1>();
        __syncwarp();

        const float* xb = mybuf0 + (size_t)buf * WT_FLOATS;
        const int r0 = wt * WT_ROWS + l;        // row A
        const int r1 = r0 + 32;                 // row B

        // ---- both rows from smem as packed pairs: 2 x 5 LDS.128 ----
        ulonglong2 xav[5], xbv[5];
        const ulonglong2* pa = reinterpret_cast<const ulonglong2*>(&xb[l * IN_DIM]);
        const ulonglong2* pb = reinterpret_cast<const ulonglong2*>(&xb[(l + 32) * IN_DIM]);
#pragma unroll
        for (int q = 0; q < 5; ++q) { xav[q] = pa[q]; xbv[q] = pb[q]; }

        // ---- layer 1: packed dual-FMA along k (20 -> 10 FFMA2 per row per j) ----
        float h1a[6], h1b[6];
#pragma unroll
        for (int j = 0; j < HID; ++j) {
            const ulonglong2* wr = reinterpret_cast<const ulonglong2*>(&sW1[j * IN_DIM]);
            u64 aa = 0ull, bb = 0ull;
#pragma unroll
            for (int q = 0; q < 5; ++q) {
                ulonglong2 wv = wr[q];
                ffma2(aa, xav[q].x, wv.x); ffma2(bb, xbv[q].x, wv.x);
                ffma2(aa, xav[q].y, wv.y); ffma2(bb, xbv[q].y, wv.y);
            }
            h1a[j] = sigmoid_t(hadd2(aa));
            h1b[j] = sigmoid_t(hadd2(bb));
        }

        // pack h1 into pairs once per row (3 movs/row), reused across 6 j's
        u64 h1ap[3] = { pack2(h1a[0], h1a[1]), pack2(h1a[2], h1a[3]), pack2(h1a[4], h1a[5]) };
        u64 h1bp[3] = { pack2(h1b[0], h1b[1]), pack2(h1b[2], h1b[3]), pack2(h1b[4], h1b[5]) };

        // ---- layer 2: 3 FFMA2 per row per j ----
        float h2a[6], h2b[6];
#pragma unroll
        for (int j = 0; j < HID; ++j) {
            const u64* wp = reinterpret_cast<const u64*>(&sW2[j * 8]);
            u64 w01 = wp[0], w23 = wp[1], w45 = wp[2];
            u64 aa = 0ull, bb = 0ull;
            ffma2(aa, h1ap[0], w01); ffma2(bb, h1bp[0], w01);
            ffma2(aa, h1ap[1], w23); ffma2(bb, h1bp[1], w23);
            ffma2(aa, h1ap[2], w45); ffma2(bb, h1bp[2], w45);
            h2a[j] = sigmoid_t(hadd2(aa));
            h2b[j] = sigmoid_t(hadd2(bb));
        }

        u64 h2ap[3] = { pack2(h2a[0], h2a[1]), pack2(h2a[2], h2a[3]), pack2(h2a[4], h2a[5]) };
        u64 h2bp[3] = { pack2(h2b[0], h2b[1]), pack2(h2b[2], h2b[3]), pack2(h2b[4], h2b[5]) };

        // ---- layer 3 (linear) ----
        float oa[OUT_DIM], ob[OUT_DIM];
#pragma unroll
        for (int j = 0; j < OUT_DIM; ++j) {
            const u64* wp = reinterpret_cast<const u64*>(&sW5[j * 8]);
            u64 w01 = wp[0], w23 = wp[1], w45 = wp[2];
            u64 aa = 0ull, bb = 0ull;
            ffma2(aa, h2ap[0], w01); ffma2(bb, h2bp[0], w01);
            ffma2(aa, h2ap[1], w23); ffma2(bb, h2bp[1], w23);
            ffma2(aa, h2ap[2], w45); ffma2(bb, h2bp[2], w45);
            oa[j] = hadd2(aa); ob[j] = hadd2(bb);
        }

        if (r0 < B) {
            float2* op = reinterpret_cast<float2*>(out + (size_t)r0 * OUT_DIM);
            stg_cs_v2(op + 0, make_float2(oa[0], oa[1]));
            stg_cs_v2(op + 1, make_float2(oa[2], oa[3]));
            stg_cs_v2(op + 2, make_float2(oa[4], oa[5]));
        }
        if (r1 < B) {
            float2* op = reinterpret_cast<float2*>(out + (size_t)r1 * OUT_DIM);
            stg_cs_v2(op + 0, make_float2(ob[0], ob[1]));
            stg_cs_v2(op + 1, make_float2(ob[2], ob[3]));
            stg_cs_v2(op + 2, make_float2(ob[4], ob[5]));
        }
        // no block barrier: buffers are warp-private; same-warp program order
        // makes the WAR on restage safe.
    }
}

extern "C" void kernel_launch(void* const* d_in, const int* in_sizes, int n_in,
                              void* d_out, int out_size)
{
    const float* x  = (const float*)d_in[0];
    const float* W1 = (const float*)d_in[1];
    const float* W2 = (const float*)d_in[2];
    const float* W5 = (const float*)d_in[3];
    float* out = (float*)d_out;

    const int B = in_sizes[0] / IN_DIM;
    const int nwt = (B + WT_ROWS - 1) / WT_ROWS;

    const size_t smem_bytes = (size_t)NWARPS * 2 * WT_FLOATS * sizeof(float);  // 40 KB
    static bool attr_set = false;
    if (!attr_set) {
        cudaFuncSetAttribute(mlp3_kernel,
                             cudaFuncAttributeMaxDynamicSharedMemorySize,
                             (int)smem_bytes);
        attr_set = true;
    }

    int blocks = 148 * 5;                 // persistent: 5 CTAs/SM, 20 warp-pipelines
    int max_blocks = (nwt + NWARPS - 1) / NWARPS;
    if (blocks > max_blocks) blocks = max_blocks;
    if (blocks < 1) blocks = 1;

    mlp3_kernel<<<blocks, THREADS, smem_bytes>>>(x, W1, W2, W5, out, B, nwt);
}

// round 8
// speedup vs baseline: 1.0302x; 1.0302x over previous
#include <cuda_runtime.h>

#define IN_DIM    20
#define HID       6
#define OUT_DIM   6
#define THREADS   128
#define ROWS_PT   2
#define TILE_ROWS (THREADS * ROWS_PT)          // 256
#define TILE_F4   (TILE_ROWS * IN_DIM / 4)     // 1280 float4 per tile
#define F4_PT     (TILE_F4 / THREADS)          // 10 per thread

typedef unsigned long long u64;

__device__ unsigned int g_ctr;                 // dynamic tile dispenser

__device__ __forceinline__ unsigned smem_u32(const void* p) {
    return (unsigned)__cvta_generic_to_shared(p);
}
__device__ __forceinline__ void cp16(unsigned dst, const void* src) {
    asm volatile("cp.async.cg.shared.global [%0], [%1], 16;\n" :: "r"(dst), "l"(src));
}
__device__ __forceinline__ void cp_commit() {
    asm volatile("cp.async.commit_group;\n" ::: "memory");
}
template <int N>
__device__ __forceinline__ void cp_wait() {
    asm volatile("cp.async.wait_group %0;\n" :: "n"(N) : "memory");
}
__device__ __forceinline__ void stg_cs_v2(float2* p, float2 v) {
    asm volatile("st.global.cs.v2.f32 [%0], {%1, %2};\n" :: "l"(p), "f"(v.x), "f"(v.y));
}

// ---- packed f32x2 helpers (ptxas never emits FFMA2 from C++) ----
__device__ __forceinline__ u64 pack2(float lo, float hi) {
    u64 r; asm("mov.b64 %0, {%1, %2};" : "=l"(r) : "f"(lo), "f"(hi)); return r;
}
__device__ __forceinline__ float hadd2(u64 v) {
    float lo, hi; asm("mov.b64 {%0, %1}, %2;" : "=f"(lo), "=f"(hi) : "l"(v));
    return lo + hi;
}
__device__ __forceinline__ void ffma2(u64& acc, u64 a, u64 b) {
    asm("fma.rn.f32x2 %0, %1, %2, %0;" : "+l"(acc) : "l"(a), "l"(b));
}

// sigmoid(z) = 0.5 * tanh(0.5 z) + 0.5   -> 1 MUFU.TANH + FMUL + FFMA
__device__ __forceinline__ float sigmoid_t(float z) {
    float th;
    asm("tanh.approx.f32 %0, %1;" : "=f"(th) : "f"(z * 0.5f));
    return fmaf(th, 0.5f, 0.5f);
}

__global__ void reset_ctr_kernel() { g_ctr = 0u; }

__global__ __launch_bounds__(THREADS, 5)
void mlp3_kernel(const float* __restrict__ x,
                 const float* __restrict__ W1,   // [HID, IN]
                 const float* __restrict__ W2,   // [HID, HID]
                 const float* __restrict__ W5,   // [OUT, HID]
                 float* __restrict__ out,        // [B, OUT]
                 int B, int ntiles)
{
    __shared__ __align__(16) float sW1[HID * IN_DIM];   // [6][20]
    __shared__ __align__(16) float sW2[HID * 8];        // [6][8] zero-padded
    __shared__ __align__(16) float sW5[OUT_DIM * 8];    // [6][8] zero-padded
    __shared__ int sNext;
    extern __shared__ __align__(16) float sX[];         // [2][TILE_ROWS*IN_DIM]

    const int t = threadIdx.x;

    if (t < HID * IN_DIM) sW1[t] = W1[t];
    if (t < HID * 8)      sW2[t] = ((t & 7) < HID) ? W2[(t >> 3) * HID + (t & 7)] : 0.0f;
    if (t < OUT_DIM * 8)  sW5[t] = ((t & 7) < HID) ? W5[(t >> 3) * HID + (t & 7)] : 0.0f;

    const size_t total_f4 = ((size_t)B * IN_DIM) >> 2;

    auto stage = [&](int tile, int buf) {
        size_t base_f4 = (size_t)tile * TILE_F4;
        const float4* src = reinterpret_cast<const float4*>(x) + base_f4;
        unsigned dst = smem_u32(&sX[(size_t)buf * (TILE_ROWS * IN_DIM)]);
#pragma unroll
        for (int q = 0; q < F4_PT; ++q) {
            int idx = t + q * THREADS;
            if (base_f4 + (size_t)idx < total_f4)
                cp16(dst + (unsigned)idx * 16, src + idx);
        }
    };

    // ---- dynamic prologue: fetch id0, stage it, fetch id1 ----
    if (t == 0) sNext = (int)atomicAdd(&g_ctr, 1u);
    __syncthreads();
    int id0 = sNext;
    if (id0 < ntiles) stage(id0, 0);
    cp_commit();
    if (t == 0) sNext = (int)atomicAdd(&g_ctr, 1u);
    __syncthreads();
    int id1 = sNext;

    int buf = 0;
    while (id0 < ntiles) {
        // prefetch id1 into the other buffer; fetch id2 under the covers
        if (id1 < ntiles) stage(id1, buf ^ 1);
        cp_commit();
        if (t == 0) sNext = (id1 < ntiles) ? (int)atomicAdd(&g_ctr, 1u) : ntiles;
        cp_wait<1>();          // id0's group complete
        __syncthreads();       // staged data + sNext visible to all

        const float* xb = &sX[(size_t)buf * (TILE_ROWS * IN_DIM)];
        const int r0 = id0 * TILE_ROWS + t;           // row A
        const int r1 = r0 + THREADS;                  // row B

        // ---- both rows from smem as packed pairs: 2 x 5 LDS.128 ----
        ulonglong2 xav[5], xbv[5];
        const ulonglong2* pa = reinterpret_cast<const ulonglong2*>(&xb[t * IN_DIM]);
        const ulonglong2* pb = reinterpret_cast<const ulonglong2*>(&xb[(t + THREADS) * IN_DIM]);
#pragma unroll
        for (int q = 0; q < 5; ++q) { xav[q] = pa[q]; xbv[q] = pb[q]; }

        // ---- layer 1: packed dual-FMA along k ----
        float h1a[6], h1b[6];
#pragma unroll
        for (int j = 0; j < HID; ++j) {
            const ulonglong2* wr = reinterpret_cast<const ulonglong2*>(&sW1[j * IN_DIM]);
            u64 aa = 0ull, bb = 0ull;
#pragma unroll
            for (int q = 0; q < 5; ++q) {
                ulonglong2 wv = wr[q];
                ffma2(aa, xav[q].x, wv.x); ffma2(bb, xbv[q].x, wv.x);
                ffma2(aa, xav[q].y, wv.y); ffma2(bb, xbv[q].y, wv.y);
            }
            h1a[j] = sigmoid_t(hadd2(aa));
            h1b[j] = sigmoid_t(hadd2(bb));
        }

        u64 h1ap[3] = { pack2(h1a[0], h1a[1]), pack2(h1a[2], h1a[3]), pack2(h1a[4], h1a[5]) };
        u64 h1bp[3] = { pack2(h1b[0], h1b[1]), pack2(h1b[2], h1b[3]), pack2(h1b[4], h1b[5]) };

        // ---- layer 2 ----
        float h2a[6], h2b[6];
#pragma unroll
        for (int j = 0; j < HID; ++j) {
            const u64* wp = reinterpret_cast<const u64*>(&sW2[j * 8]);
            u64 w01 = wp[0], w23 = wp[1], w45 = wp[2];
            u64 aa = 0ull, bb = 0ull;
            ffma2(aa, h1ap[0], w01); ffma2(bb, h1bp[0], w01);
            ffma2(aa, h1ap[1], w23); ffma2(bb, h1bp[1], w23);
            ffma2(aa, h1ap[2], w45); ffma2(bb, h1bp[2], w45);
            h2a[j] = sigmoid_t(hadd2(aa));
            h2b[j] = sigmoid_t(hadd2(bb));
        }

        u64 h2ap[3] = { pack2(h2a[0], h2a[1]), pack2(h2a[2], h2a[3]), pack2(h2a[4], h2a[5]) };
        u64 h2bp[3] = { pack2(h2b[0], h2b[1]), pack2(h2b[2], h2b[3]), pack2(h2b[4], h2b[5]) };

        // ---- layer 3 (linear) ----
        float oa[OUT_DIM], ob[OUT_DIM];
#pragma unroll
        for (int j = 0; j < OUT_DIM; ++j) {
            const u64* wp = reinterpret_cast<const u64*>(&sW5[j * 8]);
            u64 w01 = wp[0], w23 = wp[1], w45 = wp[2];
            u64 aa = 0ull, bb = 0ull;
            ffma2(aa, h2ap[0], w01); ffma2(bb, h2bp[0], w01);
            ffma2(aa, h2ap[1], w23); ffma2(bb, h2bp[1], w23);
            ffma2(aa, h2ap[2], w45); ffma2(bb, h2bp[2], w45);
            oa[j] = hadd2(aa); ob[j] = hadd2(bb);
        }

        if (r0 < B) {
            float2* op = reinterpret_cast<float2*>(out + (size_t)r0 * OUT_DIM);
            stg_cs_v2(op + 0, make_float2(oa[0], oa[1]));
            stg_cs_v2(op + 1, make_float2(oa[2], oa[3]));
            stg_cs_v2(op + 2, make_float2(oa[4], oa[5]));
        }
        if (r1 < B) {
            float2* op = reinterpret_cast<float2*>(out + (size_t)r1 * OUT_DIM);
            stg_cs_v2(op + 0, make_float2(ob[0], ob[1]));
            stg_cs_v2(op + 1, make_float2(ob[2], ob[3]));
            stg_cs_v2(op + 2, make_float2(ob[4], ob[5]));
        }

        int id2 = sNext;
        __syncthreads();       // all reads of buf + sNext consumed before restage
        id0 = id1; id1 = id2;
        buf ^= 1;
    }
}

extern "C" void kernel_launch(void* const* d_in, const int* in_sizes, int n_in,
                              void* d_out, int out_size)
{
    const float* x  = (const float*)d_in[0];
    const float* W1 = (const float*)d_in[1];
    const float* W2 = (const float*)d_in[2];
    const float* W5 = (const float*)d_in[3];
    float* out = (float*)d_out;

    const int B = in_sizes[0] / IN_DIM;
    const int ntiles = (B + TILE_ROWS - 1) / TILE_ROWS;

    const size_t smem_bytes = 2ull * TILE_ROWS * IN_DIM * sizeof(float);  // 40 KB
    static bool attr_set = false;
    if (!attr_set) {
        cudaFuncSetAttribute(mlp3_kernel,
                             cudaFuncAttributeMaxDynamicSharedMemorySize,
                             (int)smem_bytes);
        attr_set = true;
    }

    // reset the tile dispenser (kernel node — graph-capturable, deterministic)
    reset_ctr_kernel<<<1, 1>>>();

    int blocks = 148 * 5;                 // persistent: 5 CTAs/SM
    if (blocks > ntiles) blocks = ntiles;
    if (blocks < 1) blocks = 1;

    mlp3_kernel<<<blocks, THREADS, smem_bytes>>>(x, W1, W2, W5, out, B, ntiles);
}